// round 6
// baseline (speedup 1.0000x reference)
#include <cuda_runtime.h>

// ---------------------------------------------------------------------------
// MultiHeadAttentionEdge — reformulated:
//   qk[b,n,h,i] = sum_o (q[b,n,h,o]/sqrt(32)) * Wk[h,i,o]     (i in [0,192))
//   logits[b,h,n,m] = sum_{i<128} qk_i*key[b,m,i] + sum_{i<64} qk_{128+i}*edge[b,n,m,i]
//   attn = softmax_m; mh = attn @ v; out = mh @ Wp + bias
// R4: full coalescing rewrite. keyT pre-transpose; edge staged through smem
// (32B-sector coalesced loads + pitch-514 transpose); qk in [i][h] layout;
// thread owns adjacent m-pair (2t,2t+1) so key LDG.64 IS the f32x2 operand.
// ---------------------------------------------------------------------------

namespace {
constexpr int B    = 2;
constexpr int N    = 512;
constexpr int M    = 512;
constexpr int DQ   = 128;
constexpr int DK   = 128;
constexpr int DE   = 64;
constexpr int DKE  = DK + DE;   // 192
constexpr int H    = 8;
constexpr int O    = 32;
constexpr int OUTD = 128;
}

// Scratch (device globals — no allocation allowed)
__device__ __align__(16) float g_qk  [(size_t)B*N*DKE*H];   // [b][n][i][h] 6.3 MB
__device__ __align__(16) float g_keyT[(size_t)B*DK*M];      // [b][i][m] 0.5 MB
__device__ __align__(16) float g_v   [(size_t)B*M*H*O];     // [b][m][h][o] 2 MB
__device__ __align__(16) float g_attn[(size_t)B*H*N*M];     // 16.8 MB
__device__ __align__(16) float g_mh  [(size_t)B*N*H*O];     // [b][n][h][o] 2 MB

typedef unsigned long long u64;

__device__ __forceinline__ u64 pack2(float lo, float hi) {
    u64 r; asm("mov.b64 %0, {%1,%2};" : "=l"(r) : "f"(lo), "f"(hi)); return r;
}
__device__ __forceinline__ void fma2(u64& d, u64 a, u64 b) {
    asm("fma.rn.f32x2 %0, %1, %2, %0;" : "+l"(d) : "l"(a), "l"(b));
}
__device__ __forceinline__ float2 unpack2(u64 v) {
    float2 r; asm("mov.b64 {%0,%1}, %2;" : "=f"(r.x), "=f"(r.y) : "l"(v)); return r;
}

// ---------------------------------------------------------------------------
// K0: key transpose -> g_keyT[b][i][m]  (32x32 smem tiles)
// ---------------------------------------------------------------------------
__global__ __launch_bounds__(256) void k_keyT(const float* __restrict__ key) {
    __shared__ float ts[32][33];
    const int x  = blockIdx.x;             // B*16*4 = 128
    const int b  = x >> 6;
    const int mt = (x & 63) >> 2;
    const int it = x & 3;
    const int m0 = mt << 5, i0 = it << 5;
    const int t  = threadIdx.x;
    #pragma unroll
    for (int j = 0; j < 4; j++) {
        int idx = t + 256*j;
        int r = idx >> 5, c = idx & 31;
        ts[r][c] = key[((size_t)b*M + m0 + r)*DK + i0 + c];
    }
    __syncthreads();
    #pragma unroll
    for (int j = 0; j < 4; j++) {
        int idx = t + 256*j;
        int r = idx >> 5, c = idx & 31;
        g_keyT[((size_t)b*DK + i0 + r)*M + m0 + c] = ts[c][r];
    }
}

// ---------------------------------------------------------------------------
// K1a: per (b, 8-n tile): q = query@Wq / sqrt(32);  qk = q @ Wk^T(over o)
//      writes g_qk in [b][n][i][h] layout
// ---------------------------------------------------------------------------
__global__ __launch_bounds__(256) void k_qk(const float* __restrict__ query,
                                            const float* __restrict__ Wq,
                                            const float* __restrict__ Wk) {
    const int b  = blockIdx.x >> 6;
    const int n0 = (blockIdx.x & 63) << 3;
    const int t  = threadIdx.x;

    __shared__ float xs[8][DQ];
    __shared__ float qs[8][H*O];

    #pragma unroll
    for (int j = 0; j < 4; j++) {
        int idx = t + 256*j;
        int nl = idx >> 7, d = idx & 127;
        xs[nl][d] = query[((size_t)(b*N + n0 + nl))*DQ + d];
    }
    __syncthreads();

    {   // q: thread owns (h,o)
        const int h = t >> 5, o = t & 31;
        float acc[8];
        #pragma unroll
        for (int nl = 0; nl < 8; nl++) acc[nl] = 0.f;
        const float* wq = Wq + ((size_t)h*DQ)*O + o;
        for (int d = 0; d < DQ; d++) {
            float w = wq[(size_t)d*O];
            #pragma unroll
            for (int nl = 0; nl < 8; nl++) acc[nl] = fmaf(xs[nl][d], w, acc[nl]);
        }
        const float scale = 0.17677669529663688f; // 1/sqrt(32)
        #pragma unroll
        for (int nl = 0; nl < 8; nl++) qs[nl][t] = acc[nl] * scale;
    }
    __syncthreads();

    // qk: 1536 (h,i) pairs, 6 per thread, 8 n each
    #pragma unroll
    for (int j = 0; j < 6; j++) {
        int p = t + 256*j;
        int h = p / DKE, i = p - h*DKE;
        const float* wk = Wk + ((size_t)h*DKE + i)*O;
        float acc[8];
        #pragma unroll
        for (int nl = 0; nl < 8; nl++) acc[nl] = 0.f;
        for (int o = 0; o < O; o++) {
            float w = wk[o];
            #pragma unroll
            for (int nl = 0; nl < 8; nl++) acc[nl] = fmaf(qs[nl][h*O + o], w, acc[nl]);
        }
        #pragma unroll
        for (int nl = 0; nl < 8; nl++)
            g_qk[((size_t)(b*N + n0 + nl)*DKE + i)*H + h] = acc[nl];
    }
}

// ---------------------------------------------------------------------------
// K1b: v[b,m,h,o] = value @ Wv
// ---------------------------------------------------------------------------
__global__ __launch_bounds__(256) void k_v(const float* __restrict__ value,
                                           const float* __restrict__ Wv) {
    const int b  = blockIdx.x >> 6;
    const int m0 = (blockIdx.x & 63) << 3;
    const int t  = threadIdx.x;

    __shared__ float xs[8][DK];
    #pragma unroll
    for (int j = 0; j < 4; j++) {
        int idx = t + 256*j;
        int ml = idx >> 7, d = idx & 127;
        xs[ml][d] = value[((size_t)(b*M + m0 + ml))*DK + d];
    }
    __syncthreads();

    const int h = t >> 5, o = t & 31;
    float acc[8];
    #pragma unroll
    for (int ml = 0; ml < 8; ml++) acc[ml] = 0.f;
    const float* wv = Wv + ((size_t)h*DK)*O + o;
    for (int d = 0; d < DK; d++) {
        float w = wv[(size_t)d*O];
        #pragma unroll
        for (int ml = 0; ml < 8; ml++) acc[ml] = fmaf(xs[ml][d], w, acc[ml]);
    }
    #pragma unroll
    for (int ml = 0; ml < 8; ml++)
        g_v[(((size_t)(b*M + m0 + ml))*H + h)*O + o] = acc[ml];
}

// ---------------------------------------------------------------------------
// K2: per (b,n): logits (key via coalesced keyT LDG.64 = f32x2 operand;
//     edge via smem transpose), fused softmax, coalesced attn write.
//     Thread owns m-pair (2t, 2t+1); acc[h] packs both m's.
// ---------------------------------------------------------------------------
__global__ __launch_bounds__(256) void k_attn(const float* __restrict__ edge) {
    __shared__ __align__(16) u64   qk2[DKE*H];   // [i][h] replicated {q,q}, 12.3 KB
    __shared__ __align__(16) float xs[8][514];   // edge i-slice transposed, 16.4 KB
    __shared__ __align__(16) float lg[H*M];      // [h][m], 16 KB
    __shared__ float rinv[H];

    const int bn = blockIdx.x;     // b*N + n
    const int b  = bn >> 9;
    const int n  = bn & 511;
    const int t  = threadIdx.x;

    // qk load (coalesced: gmem layout is [i][h] flat) + replicate to pairs
    const float* qkp = g_qk + (size_t)bn * (DKE*H);
    #pragma unroll
    for (int j = 0; j < 6; j++) {
        int idx = t + 256*j;
        float v = qkp[idx];
        qk2[idx] = pack2(v, v);
    }
    __syncthreads();

    u64 acc[H];
    #pragma unroll
    for (int h = 0; h < H; h++) acc[h] = 0ull;

    // ---- key phase: i in [0,128), keyT[b][i][2t..2t+1] is the operand ----
    {
        const u64* kT = (const u64*)(g_keyT + (size_t)b*DK*M) + t;
        #pragma unroll 4
        for (int i = 0; i < DK; i++) {
            u64 p = kT[(size_t)i*(M/2)];
            const ulonglong2* q = (const ulonglong2*)(qk2 + i*H);
            ulonglong2 q0 = q[0], q1 = q[1], q2 = q[2], q3 = q[3];
            fma2(acc[0], q0.x, p); fma2(acc[1], q0.y, p);
            fma2(acc[2], q1.x, p); fma2(acc[3], q1.y, p);
            fma2(acc[4], q2.x, p); fma2(acc[5], q2.y, p);
            fma2(acc[6], q3.x, p); fma2(acc[7], q3.y, p);
        }
    }

    // ---- edge phase: 8 slices of 8 i's, staged+transposed through smem ----
    for (int sub = 0; sub < 8; sub++) {
        __syncthreads();
        #pragma unroll
        for (int j = 0; j < 4; j++) {
            int idx = t + 256*j;            // 0..1023
            int m = idx >> 1, c = idx & 1;  // 2 float4 per m-row slice of 8
            float4 v = *(const float4*)(edge + ((size_t)bn*M + m)*DE + sub*8 + c*4);
            int si = c*4;
            xs[si+0][m] = v.x; xs[si+1][m] = v.y;
            xs[si+2][m] = v.z; xs[si+3][m] = v.w;
        }
        __syncthreads();
        #pragma unroll
        for (int il = 0; il < 8; il++) {
            int i = DK + sub*8 + il;
            u64 p = *(const u64*)(&xs[il][2*t]);
            const ulonglong2* q = (const ulonglong2*)(qk2 + i*H);
            ulonglong2 q0 = q[0], q1 = q[1], q2 = q[2], q3 = q[3];
            fma2(acc[0], q0.x, p); fma2(acc[1], q0.y, p);
            fma2(acc[2], q1.x, p); fma2(acc[3], q1.y, p);
            fma2(acc[4], q2.x, p); fma2(acc[5], q2.y, p);
            fma2(acc[6], q3.x, p); fma2(acc[7], q3.y, p);
        }
    }

    #pragma unroll
    for (int h = 0; h < H; h++) {
        float2 v = unpack2(acc[h]);
        *(float2*)(lg + h*M + 2*t) = v;
    }
    __syncthreads();

    // softmax: warp w handles head h=w
    {
        const int h = t >> 5, l = t & 31;
        float* lh = lg + h*M;
        float v[16];
        #pragma unroll
        for (int j = 0; j < 16; j++) v[j] = lh[l + 32*j];
        float mx = v[0];
        #pragma unroll
        for (int j = 1; j < 16; j++) mx = fmaxf(mx, v[j]);
        #pragma unroll
        for (int s = 16; s > 0; s >>= 1) mx = fmaxf(mx, __shfl_xor_sync(0xffffffffu, mx, s));
        float sum = 0.f;
        #pragma unroll
        for (int j = 0; j < 16; j++) {
            float e = __expf(v[j] - mx);
            lh[l + 32*j] = e;
            sum += e;
        }
        #pragma unroll
        for (int s = 16; s > 0; s >>= 1) sum += __shfl_xor_sync(0xffffffffu, sum, s);
        if (l == 0) rinv[h] = 1.f / sum;
    }
    __syncthreads();

    #pragma unroll
    for (int h = 0; h < H; h++) {
        float inv = rinv[h];
        float2 e = *(const float2*)(lg + h*M + 2*t);
        float2 o2 = make_float2(e.x * inv, e.y * inv);
        *(float2*)(g_attn + (((size_t)b*H + h)*N + n)*M + 2*t) = o2;
    }
}

// ---------------------------------------------------------------------------
// K3: mh[b,n,h,o] = sum_m attn[b,h,n,m] * v[b,m,h,o]
//     256 blocks = (b, h, 32-n tile); m chunks of 128; f32x2 accumulators.
// ---------------------------------------------------------------------------
__global__ __launch_bounds__(256) void k_av() {
    const int x  = blockIdx.x;           // 2*8*16 = 256
    const int b  = x >> 7;
    const int h  = (x >> 4) & 7;
    const int n0 = (x & 15) << 5;
    const int t  = threadIdx.x;
    const int nl = t >> 3;               // 0..31 local n
    const int og = t & 7;                // o-group (4 o's)

    __shared__ __align__(16) float at[32][132];   // pitch 132: conflict-free
    __shared__ __align__(16) float vt[128][32];

    u64 a01 = 0ull, a23 = 0ull;

    for (int mt = 0; mt < 4; mt++) {
        const int mb = mt << 7;
        #pragma unroll
        for (int j = 0; j < 4; j++) {    // attn tile 32x128 = 1024 float4
            int idx = t + 256*j;
            int r = idx >> 5, c = idx & 31;
            *(float4*)&at[r][c*4] =
                *(const float4*)(g_attn + (((size_t)b*H + h)*N + n0 + r)*M + mb + c*4);
        }
        #pragma unroll
        for (int j = 0; j < 4; j++) {    // v tile 128x32 = 1024 float4
            int idx = t + 256*j;
            int ml = idx >> 3, c = idx & 7;
            *(float4*)&vt[ml][c*4] =
                *(const float4*)(g_v + (((size_t)b*M + mb + ml)*H + h)*O + c*4);
        }
        __syncthreads();
        #pragma unroll 4
        for (int m = 0; m < 128; m++) {
            float a = at[nl][m];
            u64 a2 = pack2(a, a);
            const u64* vv = (const u64*)&vt[m][og*4];
            fma2(a01, a2, vv[0]);
            fma2(a23, a2, vv[1]);
        }
        __syncthreads();
    }
    float2 x01 = unpack2(a01), x23 = unpack2(a23);
    float4 outv = make_float4(x01.x, x01.y, x23.x, x23.y);
    *(float4*)&g_mh[((size_t)(b*N + n0 + nl)*H + h)*O + og*4] = outv;
}

// ---------------------------------------------------------------------------
// K4: out[b,n,j] = sum_k mh[b,n,k] * Wp[k,j] + bias[j]
// ---------------------------------------------------------------------------
__global__ __launch_bounds__(256) void k_proj(const float* __restrict__ Wp,
                                              const float* __restrict__ bias,
                                              float* __restrict__ out) {
    const int b  = blockIdx.x >> 6;
    const int n0 = (blockIdx.x & 63) << 3;
    const int t  = threadIdx.x;

    __shared__ float mh[8][H*O];
    #pragma unroll
    for (int j = 0; j < 8; j++) {
        int idx = t + 256*j;
        int nl = idx >> 8, c = idx & 255;
        mh[nl][c] = g_mh[((size_t)(b*N + n0 + nl))*(H*O) + c];
    }
    __syncthreads();

    const int jj = t & 127, half = t >> 7;
    const float bv = bias[jj];
    #pragma unroll
    for (int pass = 0; pass < 4; pass++) {
        int nl = half + 2*pass;
        float acc = 0.f;
        for (int k = 0; k < H*O; k++)
            acc = fmaf(mh[nl][k], Wp[(size_t)k*OUTD + jj], acc);
        out[((size_t)(b*N + n0 + nl))*OUTD + jj] = acc + bv;
    }
}

// ---------------------------------------------------------------------------
extern "C" void kernel_launch(void* const* d_in, const int* in_sizes, int n_in,
                              void* d_out, int out_size) {
    (void)in_sizes; (void)n_in; (void)out_size;
    const float* query = (const float*)d_in[0];
    const float* key   = (const float*)d_in[1];
    const float* value = (const float*)d_in[2];
    const float* edge  = (const float*)d_in[3];
    const float* Wq    = (const float*)d_in[4];
    const float* Wk    = (const float*)d_in[5];
    const float* Wv    = (const float*)d_in[6];
    const float* Wp    = (const float*)d_in[7];
    const float* bias  = (const float*)d_in[8];
    float* out = (float*)d_out;

    k_keyT<<<B*16*4,       256>>>(key);
    k_qk  <<<B*(N/8),      256>>>(query, Wq, Wk);
    k_v   <<<B*(M/8),      256>>>(value, Wv);
    k_attn<<<B*N,          256>>>(edge);
    k_av  <<<B*H*(N/32),   256>>>();
    k_proj<<<B*(N/8),      256>>>(Wp, bias, out);
}

// round 7
// speedup vs baseline: 1.0562x; 1.0562x over previous
#include <cuda_runtime.h>

namespace {
constexpr int B=2, N=512, M=512, DQ=128, DK=128, DE=64, DKE=192, H=8, O=32, OUTD=128;
}

__device__ __align__(16) float g_qk  [(size_t)B*N*DKE*H];   // [b][n][i][h]
__device__ __align__(16) float g_keyT[(size_t)B*DK*M];      // [b][i][m]
__device__ __align__(16) float g_v   [(size_t)B*M*H*O];     // [b][m][h][o]
__device__ __align__(16) float g_attn[(size_t)B*H*N*M];
__device__ __align__(16) float g_mh  [(size_t)B*N*H*O];

typedef unsigned long long u64;
__device__ __forceinline__ u64 pack2(float lo, float hi) {
    u64 r; asm("mov.b64 %0, {%1,%2};" : "=l"(r) : "f"(lo), "f"(hi)); return r;
}
__device__ __forceinline__ void fma2(u64& d, u64 a, u64 b) {
    asm("fma.rn.f32x2 %0, %1, %2, %0;" : "+l"(d) : "l"(a), "l"(b));
}
__device__ __forceinline__ float2 unpack2(u64 v) {
    float2 r; asm("mov.b64 {%0,%1}, %2;" : "=f"(r.x), "=f"(r.y) : "l"(v)); return r;
}

// K0: key transpose -> g_keyT[b][i][m]
__global__ __launch_bounds__(256) void k_keyT(const float* __restrict__ key) {
    __shared__ float ts[32][33];
    const int x=blockIdx.x, b=x>>6, mt=(x&63)>>2, it=x&3;
    const int m0=mt<<5, i0=it<<5, t=threadIdx.x;
    #pragma unroll
    for (int j=0;j<4;j++){int idx=t+256*j,r=idx>>5,c=idx&31;
        ts[r][c]=key[((size_t)b*M+m0+r)*DK+i0+c];}
    __syncthreads();
    #pragma unroll
    for (int j=0;j<4;j++){int idx=t+256*j,r=idx>>5,c=idx&31;
        g_keyT[((size_t)b*DK+i0+r)*M+m0+c]=ts[c][r];}
}

// K1a: q = query@Wq/sqrt(32); qk = q@Wk^T -> g_qk [b][n][i][h]
__global__ __launch_bounds__(256) void k_qk(const float* __restrict__ query,
                                            const float* __restrict__ Wq,
                                            const float* __restrict__ Wk) {
    const int b=blockIdx.x>>6, n0=(blockIdx.x&63)<<3, t=threadIdx.x;
    __shared__ float xs[8][DQ];
    __shared__ float qs[8][H*O];
    #pragma unroll
    for (int j=0;j<4;j++){int idx=t+256*j,nl=idx>>7,d=idx&127;
        xs[nl][d]=query[((size_t)(b*N+n0+nl))*DQ+d];}
    __syncthreads();
    {
        const int h=t>>5,o=t&31;
        float acc[8];
        #pragma unroll
        for (int nl=0;nl<8;nl++) acc[nl]=0.f;
        const float* wq=Wq+((size_t)h*DQ)*O+o;
        for (int d=0;d<DQ;d++){float w=wq[(size_t)d*O];
            #pragma unroll
            for (int nl=0;nl<8;nl++) acc[nl]=fmaf(xs[nl][d],w,acc[nl]);}
        const float scale=0.17677669529663688f;
        #pragma unroll
        for (int nl=0;nl<8;nl++) qs[nl][t]=acc[nl]*scale;
    }
    __syncthreads();
    #pragma unroll
    for (int j=0;j<6;j++){
        int p=t+256*j,h=p/DKE,i=p-h*DKE;
        const float* wk=Wk+((size_t)h*DKE+i)*O;
        float acc[8];
        #pragma unroll
        for (int nl=0;nl<8;nl++) acc[nl]=0.f;
        for (int o=0;o<O;o++){float w=wk[o];
            #pragma unroll
            for (int nl=0;nl<8;nl++) acc[nl]=fmaf(qs[nl][h*O+o],w,acc[nl]);}
        #pragma unroll
        for (int nl=0;nl<8;nl++)
            g_qk[((size_t)(b*N+n0+nl)*DKE+i)*H+h]=acc[nl];
    }
}

// K1b: v = value@Wv -> g_v [b][m][h][o]
__global__ __launch_bounds__(256) void k_v(const float* __restrict__ value,
                                           const float* __restrict__ Wv) {
    const int b=blockIdx.x>>6, m0=(blockIdx.x&63)<<3, t=threadIdx.x;
    __shared__ float xs[8][DK];
    #pragma unroll
    for (int j=0;j<4;j++){int idx=t+256*j,ml=idx>>7,d=idx&127;
        xs[ml][d]=value[((size_t)(b*M+m0+ml))*DK+d];}
    __syncthreads();
    const int h=t>>5,o=t&31;
    float acc[8];
    #pragma unroll
    for (int ml=0;ml<8;ml++) acc[ml]=0.f;
    const float* wv=Wv+((size_t)h*DK)*O+o;
    for (int d=0;d<DK;d++){float w=wv[(size_t)d*O];
        #pragma unroll
        for (int ml=0;ml<8;ml++) acc[ml]=fmaf(xs[ml][d],w,acc[ml]);}
    #pragma unroll
    for (int ml=0;ml<8;ml++)
        g_v[(((size_t)(b*M+m0+ml))*H+h)*O+o]=acc[ml];
}

// K2 v3: block = 2 n, 128 threads, thread owns m-quad 4t..4t+3.
// qk float in smem, packed on the fly; 32 fma2 per key-X LDG.128.
// Edge: 16-i slices, rot-8c swizzle (conflict-free STS + LDS.128).
// Softmax in registers.
__global__ __launch_bounds__(128) void k_attn(const float* __restrict__ edge) {
    __shared__ __align__(16) float qkf[2*DKE*H];   // 12 KB [n][i][h]
    __shared__ __align__(16) float xs[16*512];     // 32 KB slice
    __shared__ float redA[16*4], redB[16*4];

    const int x=blockIdx.x;            // B*N/2 = 512
    const int b=x>>8, n0=(x&255)<<1, t=threadIdx.x;
    const int w=t>>5, l=t&31;

    const float* gq=g_qk+(size_t)(b*N+n0)*(DKE*H);
    #pragma unroll
    for (int j=0;j<24;j++) qkf[t+128*j]=gq[t+128*j];
    __syncthreads();

    u64 acc[2][8][2];
    #pragma unroll
    for (int n=0;n<2;n++)
        #pragma unroll
        for (int h=0;h<8;h++){acc[n][h][0]=0ull;acc[n][h][1]=0ull;}

    // ---- key phase ----
    const ulonglong2* kT=(const ulonglong2*)(g_keyT+(size_t)b*DK*M);
    #pragma unroll 2
    for (int i=0;i<DK;i++){
        ulonglong2 X=kT[i*(M/4)+t];
        #pragma unroll
        for (int n=0;n<2;n++){
            const float4* A=(const float4*)(qkf+(n*DKE+i)*8);
            float4 a0=A[0],a1=A[1];
            u64 q0=pack2(a0.x,a0.x),q1=pack2(a0.y,a0.y);
            u64 q2=pack2(a0.z,a0.z),q3=pack2(a0.w,a0.w);
            u64 q4=pack2(a1.x,a1.x),q5=pack2(a1.y,a1.y);
            u64 q6=pack2(a1.z,a1.z),q7=pack2(a1.w,a1.w);
            fma2(acc[n][0][0],q0,X.x); fma2(acc[n][0][1],q0,X.y);
            fma2(acc[n][1][0],q1,X.x); fma2(acc[n][1][1],q1,X.y);
            fma2(acc[n][2][0],q2,X.x); fma2(acc[n][2][1],q2,X.y);
            fma2(acc[n][3][0],q3,X.x); fma2(acc[n][3][1],q3,X.y);
            fma2(acc[n][4][0],q4,X.x); fma2(acc[n][4][1],q4,X.y);
            fma2(acc[n][5][0],q5,X.x); fma2(acc[n][5][1],q5,X.y);
            fma2(acc[n][6][0],q6,X.x); fma2(acc[n][6][1],q6,X.y);
            fma2(acc[n][7][0],q7,X.x); fma2(acc[n][7][1],q7,X.y);
        }
    }

    // ---- edge phase: per n, 4 slices of 16 i ----
    for (int n=0;n<2;n++){
        const float* eb=edge+((size_t)(b*N+n0+n)*M)*DE;
        for (int s=0;s<4;s++){
            __syncthreads();
            #pragma unroll
            for (int r=0;r<16;r++){
                int id=r*128+t, m=id>>2, c=id&3;
                float4 v=*(const float4*)(eb+(size_t)m*DE+s*16+4*c);
                int col=(m+8*c)&511;
                xs[(4*c+0)*512+col]=v.x;
                xs[(4*c+1)*512+col]=v.y;
                xs[(4*c+2)*512+col]=v.z;
                xs[(4*c+3)*512+col]=v.w;
            }
            __syncthreads();
            #pragma unroll
            for (int il=0;il<16;il++){
                int col=(4*t+8*(il>>2))&511;
                ulonglong2 X=*(const ulonglong2*)(xs+il*512+col);
                const float4* A=(const float4*)(qkf+(n*DKE+DK+s*16+il)*8);
                float4 a0=A[0],a1=A[1];
                u64 q0=pack2(a0.x,a0.x),q1=pack2(a0.y,a0.y);
                u64 q2=pack2(a0.z,a0.z),q3=pack2(a0.w,a0.w);
                u64 q4=pack2(a1.x,a1.x),q5=pack2(a1.y,a1.y);
                u64 q6=pack2(a1.z,a1.z),q7=pack2(a1.w,a1.w);
                fma2(acc[n][0][0],q0,X.x); fma2(acc[n][0][1],q0,X.y);
                fma2(acc[n][1][0],q1,X.x); fma2(acc[n][1][1],q1,X.y);
                fma2(acc[n][2][0],q2,X.x); fma2(acc[n][2][1],q2,X.y);
                fma2(acc[n][3][0],q3,X.x); fma2(acc[n][3][1],q3,X.y);
                fma2(acc[n][4][0],q4,X.x); fma2(acc[n][4][1],q4,X.y);
                fma2(acc[n][5][0],q5,X.x); fma2(acc[n][5][1],q5,X.y);
                fma2(acc[n][6][0],q6,X.x); fma2(acc[n][6][1],q6,X.y);
                fma2(acc[n][7][0],q7,X.x); fma2(acc[n][7][1],q7,X.y);
            }
        }
    }
    __syncthreads();

    // ---- softmax over m (register logits) ----
    #pragma unroll
    for (int n=0;n<2;n++)
        #pragma unroll
        for (int h=0;h<8;h++){
            float2 p0=unpack2(acc[n][h][0]), p1=unpack2(acc[n][h][1]);
            float mx=fmaxf(fmaxf(p0.x,p0.y),fmaxf(p1.x,p1.y));
            #pragma unroll
            for (int s=16;s>0;s>>=1) mx=fmaxf(mx,__shfl_xor_sync(0xffffffffu,mx,s));
            if (l==0) redA[(n*8+h)*4+w]=mx;
        }
    __syncthreads();
    #pragma unroll
    for (int n=0;n<2;n++)
        #pragma unroll
        for (int h=0;h<8;h++){
            const int c=n*8+h;
            float gm=fmaxf(fmaxf(redA[c*4+0],redA[c*4+1]),
                           fmaxf(redA[c*4+2],redA[c*4+3]));
            float2 p0=unpack2(acc[n][h][0]), p1=unpack2(acc[n][h][1]);
            p0.x=__expf(p0.x-gm); p0.y=__expf(p0.y-gm);
            p1.x=__expf(p1.x-gm); p1.y=__expf(p1.y-gm);
            acc[n][h][0]=pack2(p0.x,p0.y);
            acc[n][h][1]=pack2(p1.x,p1.y);
            float sum=(p0.x+p0.y)+(p1.x+p1.y);
            #pragma unroll
            for (int s=16;s>0;s>>=1) sum+=__shfl_xor_sync(0xffffffffu,sum,s);
            if (l==0) redB[c*4+w]=sum;
        }
    __syncthreads();
    #pragma unroll
    for (int n=0;n<2;n++)
        #pragma unroll
        for (int h=0;h<8;h++){
            const int c=n*8+h;
            float inv=1.f/(redB[c*4+0]+redB[c*4+1]+redB[c*4+2]+redB[c*4+3]);
            float2 p0=unpack2(acc[n][h][0]), p1=unpack2(acc[n][h][1]);
            float4 o=make_float4(p0.x*inv,p0.y*inv,p1.x*inv,p1.y*inv);
            *(float4*)(g_attn+(((size_t)b*H+h)*N+n0+n)*M+4*t)=o;
        }
}

// K3: mh = attn @ v
__global__ __launch_bounds__(256) void k_av() {
    const int x=blockIdx.x, b=x>>7, h=(x>>4)&7, n0=(x&15)<<5;
    const int t=threadIdx.x, nl=t>>3, og=t&7;
    __shared__ __align__(16) float at[32][132];
    __shared__ __align__(16) float vt[128][32];
    u64 a01=0ull, a23=0ull;
    for (int mt=0;mt<4;mt++){
        const int mb=mt<<7;
        #pragma unroll
        for (int j=0;j<4;j++){int idx=t+256*j,r=idx>>5,c=idx&31;
            *(float4*)&at[r][c*4]=
                *(const float4*)(g_attn+(((size_t)b*H+h)*N+n0+r)*M+mb+c*4);}
        #pragma unroll
        for (int j=0;j<4;j++){int idx=t+256*j,ml=idx>>3,c=idx&7;
            *(float4*)&vt[ml][c*4]=
                *(const float4*)(g_v+(((size_t)b*M+mb+ml)*H+h)*O+c*4);}
        __syncthreads();
        #pragma unroll 4
        for (int m=0;m<128;m++){
            float a=at[nl][m];
            u64 a2=pack2(a,a);
            const u64* vv=(const u64*)&vt[m][og*4];
            fma2(a01,a2,vv[0]);
            fma2(a23,a2,vv[1]);
        }
        __syncthreads();
    }
    float2 x01=unpack2(a01), x23=unpack2(a23);
    float4 outv=make_float4(x01.x,x01.y,x23.x,x23.y);
    *(float4*)&g_mh[((size_t)(b*N+n0+nl)*H+h)*O+og*4]=outv;
}

// K4: out = mh @ Wp + bias
__global__ __launch_bounds__(256) void k_proj(const float* __restrict__ Wp,
                                              const float* __restrict__ bias,
                                              float* __restrict__ out) {
    const int b=blockIdx.x>>6, n0=(blockIdx.x&63)<<3, t=threadIdx.x;
    __shared__ float mh[8][H*O];
    #pragma unroll
    for (int j=0;j<8;j++){int idx=t+256*j,nl=idx>>8,c=idx&255;
        mh[nl][c]=g_mh[((size_t)(b*N+n0+nl))*(H*O)+c];}
    __syncthreads();
    const int jj=t&127, half=t>>7;
    const float bv=bias[jj];
    #pragma unroll
    for (int pass=0;pass<4;pass++){
        int nl=half+2*pass;
        float acc=0.f;
        for (int k=0;k<H*O;k++)
            acc=fmaf(mh[nl][k],Wp[(size_t)k*OUTD+jj],acc);
        out[((size_t)(b*N+n0+nl))*OUTD+jj]=acc+bv;
    }
}

extern "C" void kernel_launch(void* const* d_in, const int* in_sizes, int n_in,
                              void* d_out, int out_size) {
    (void)in_sizes; (void)n_in; (void)out_size;
    const float* query=(const float*)d_in[0];
    const float* key  =(const float*)d_in[1];
    const float* value=(const float*)d_in[2];
    const float* edge =(const float*)d_in[3];
    const float* Wq   =(const float*)d_in[4];
    const float* Wk   =(const float*)d_in[5];
    const float* Wv   =(const float*)d_in[6];
    const float* Wp   =(const float*)d_in[7];
    const float* bias =(const float*)d_in[8];
    float* out=(float*)d_out;

    k_keyT<<<B*16*4,     256>>>(key);
    k_qk  <<<B*(N/8),    256>>>(query,Wq,Wk);
    k_v   <<<B*(M/8),    256>>>(value,Wv);
    k_attn<<<B*(N/2),    128>>>(edge);
    k_av  <<<B*H*(N/32), 256>>>();
    k_proj<<<B*(N/8),    256>>>(Wp,bias,out);
}

// round 8
// speedup vs baseline: 1.2317x; 1.1661x over previous
#include <cuda_runtime.h>

namespace {
constexpr int B=2, N=512, M=512, DQ=128, DK=128, DE=64, DKE=192, H=8, O=32, OUTD=128;
}

__device__ __align__(16) float g_qk  [(size_t)B*N*DKE*H];   // [b][n][i][h]
__device__ __align__(16) float g_keyT[(size_t)B*DK*M];      // [b][i][m]
__device__ __align__(16) float g_v   [(size_t)B*M*H*O];     // [b][m][h][o]
__device__ __align__(16) float g_attn[(size_t)B*H*N*M];
__device__ __align__(16) float g_mh  [(size_t)B*N*H*O];

typedef unsigned long long u64;
__device__ __forceinline__ u64 pack2(float lo, float hi) {
    u64 r; asm("mov.b64 %0, {%1,%2};" : "=l"(r) : "f"(lo), "f"(hi)); return r;
}
__device__ __forceinline__ void fma2(u64& d, u64 a, u64 b) {
    asm("fma.rn.f32x2 %0, %1, %2, %0;" : "+l"(d) : "l"(a), "l"(b));
}
__device__ __forceinline__ float2 unpack2(u64 v) {
    float2 r; asm("mov.b64 {%0,%1}, %2;" : "=f"(r.x), "=f"(r.y) : "l"(v)); return r;
}

// ---------------------------------------------------------------------------
// K_pre: fused keyT (blocks 0..127) | qk (128..255) | v (256..383)
// ---------------------------------------------------------------------------
__global__ __launch_bounds__(256) void k_pre(const float* __restrict__ key,
                                             const float* __restrict__ query,
                                             const float* __restrict__ Wq,
                                             const float* __restrict__ Wk,
                                             const float* __restrict__ value,
                                             const float* __restrict__ Wv) {
    __shared__ float sm[3072];
    const int t = threadIdx.x;

    if (blockIdx.x < 128) {            // ---- keyT: 32x32 transpose tiles ----
        float (*ts)[33] = (float(*)[33])sm;
        const int x=blockIdx.x, b=x>>6, mt=(x&63)>>2, it=x&3;
        const int m0=mt<<5, i0=it<<5;
        #pragma unroll
        for (int j=0;j<4;j++){int idx=t+256*j,r=idx>>5,c=idx&31;
            ts[r][c]=key[((size_t)b*M+m0+r)*DK+i0+c];}
        __syncthreads();
        #pragma unroll
        for (int j=0;j<4;j++){int idx=t+256*j,r=idx>>5,c=idx&31;
            g_keyT[((size_t)b*DK+i0+r)*M+m0+c]=ts[c][r];}
    } else if (blockIdx.x < 256) {     // ---- qk ----
        float (*xs)[DQ]  = (float(*)[DQ])sm;
        float (*qs)[H*O] = (float(*)[H*O])(sm + 8*DQ);
        const int xb=blockIdx.x-128, b=xb>>6, n0=(xb&63)<<3;
        #pragma unroll
        for (int j=0;j<4;j++){int idx=t+256*j,nl=idx>>7,d=idx&127;
            xs[nl][d]=query[((size_t)(b*N+n0+nl))*DQ+d];}
        __syncthreads();
        {
            const int h=t>>5,o=t&31;
            float acc[8];
            #pragma unroll
            for (int nl=0;nl<8;nl++) acc[nl]=0.f;
            const float* wq=Wq+((size_t)h*DQ)*O+o;
            for (int d=0;d<DQ;d++){float w=wq[(size_t)d*O];
                #pragma unroll
                for (int nl=0;nl<8;nl++) acc[nl]=fmaf(xs[nl][d],w,acc[nl]);}
            const float scale=0.17677669529663688f; // 1/sqrt(32)
            #pragma unroll
            for (int nl=0;nl<8;nl++) qs[nl][t]=acc[nl]*scale;
        }
        __syncthreads();
        #pragma unroll
        for (int j=0;j<6;j++){
            int p=t+256*j,h=p/DKE,i=p-h*DKE;
            const float* wk=Wk+((size_t)h*DKE+i)*O;
            float acc[8];
            #pragma unroll
            for (int nl=0;nl<8;nl++) acc[nl]=0.f;
            for (int o=0;o<O;o++){float w=wk[o];
                #pragma unroll
                for (int nl=0;nl<8;nl++) acc[nl]=fmaf(qs[nl][h*O+o],w,acc[nl]);}
            #pragma unroll
            for (int nl=0;nl<8;nl++)
                g_qk[((size_t)(b*N+n0+nl)*DKE+i)*H+h]=acc[nl];
        }
    } else {                           // ---- v ----
        float (*xs)[DK] = (float(*)[DK])sm;
        const int xb=blockIdx.x-256, b=xb>>6, m0=(xb&63)<<3;
        #pragma unroll
        for (int j=0;j<4;j++){int idx=t+256*j,ml=idx>>7,d=idx&127;
            xs[ml][d]=value[((size_t)(b*M+m0+ml))*DK+d];}
        __syncthreads();
        const int h=t>>5,o=t&31;
        float acc[8];
        #pragma unroll
        for (int ml=0;ml<8;ml++) acc[ml]=0.f;
        const float* wv=Wv+((size_t)h*DK)*O+o;
        for (int d=0;d<DK;d++){float w=wv[(size_t)d*O];
            #pragma unroll
            for (int ml=0;ml<8;ml++) acc[ml]=fmaf(xs[ml][d],w,acc[ml]);}
        #pragma unroll
        for (int ml=0;ml<8;ml++)
            g_v[(((size_t)(b*M+m0+ml))*H+h)*O+o]=acc[ml];
    }
}

// ---------------------------------------------------------------------------
// K2 v4: block = 2 n, 128 threads, thread owns m-quad 4t..4t+3.
// A = pre-replicated {q,q} u64 pairs in smem (no packs, low reg pressure).
// Per warp-i: 8 broadcast LDS.128 + LDG.128 feed 32 FFMA2.
// Edge: 8-i slices, pitch-516 smem (conflict-free STS scatter + LDS.128).
// Softmax in registers; attn write as float4.
// ---------------------------------------------------------------------------
__global__ __launch_bounds__(128,4) void k_attn(const float* __restrict__ edge) {
    __shared__ __align__(16) u64   qk2[2*DKE*H];   // 24.6 KB [n][i][h] pairs
    __shared__ __align__(16) float xs[8*516];      // 16.5 KB edge slice [i][m]
    __shared__ float redA[16*4], redB[16*4];

    const int x=blockIdx.x;            // B*N/2 = 512
    const int b=x>>8, n0=(x&255)<<1, t=threadIdx.x;
    const int w=t>>5, l=t&31;

    const float* gq=g_qk+(size_t)(b*N+n0)*(DKE*H);
    #pragma unroll
    for (int j=0;j<24;j++){float v=gq[t+128*j]; qk2[t+128*j]=pack2(v,v);}
    __syncthreads();

    u64 acc[2][8][2];
    #pragma unroll
    for (int n=0;n<2;n++)
        #pragma unroll
        for (int h=0;h<8;h++){acc[n][h][0]=0ull;acc[n][h][1]=0ull;}

    // ---- key phase: X = keyT[b][i][4t..4t+3] (coalesced ulonglong2) ----
    {
        const ulonglong2* kT=(const ulonglong2*)(g_keyT+(size_t)b*DK*M);
        #pragma unroll 2
        for (int i=0;i<DK;i++){
            ulonglong2 X=kT[i*(M/4)+t];
            #pragma unroll
            for (int n=0;n<2;n++){
                const ulonglong2* A=(const ulonglong2*)(qk2+(n*DKE+i)*8);
                ulonglong2 a0=A[0],a1=A[1],a2=A[2],a3=A[3];
                fma2(acc[n][0][0],a0.x,X.x); fma2(acc[n][0][1],a0.x,X.y);
                fma2(acc[n][1][0],a0.y,X.x); fma2(acc[n][1][1],a0.y,X.y);
                fma2(acc[n][2][0],a1.x,X.x); fma2(acc[n][2][1],a1.x,X.y);
                fma2(acc[n][3][0],a1.y,X.x); fma2(acc[n][3][1],a1.y,X.y);
                fma2(acc[n][4][0],a2.x,X.x); fma2(acc[n][4][1],a2.x,X.y);
                fma2(acc[n][5][0],a2.y,X.x); fma2(acc[n][5][1],a2.y,X.y);
                fma2(acc[n][6][0],a3.x,X.x); fma2(acc[n][6][1],a3.x,X.y);
                fma2(acc[n][7][0],a3.y,X.x); fma2(acc[n][7][1],a3.y,X.y);
            }
        }
    }

    // ---- edge phase: per n, 8 slices of 8 i ----
    for (int n=0;n<2;n++){
        const float* eb=edge+((size_t)(b*N+n0+n)*M)*DE;
        for (int s=0;s<8;s++){
            __syncthreads();
            #pragma unroll
            for (int r=0;r<8;r++){
                int id=r*128+t, m=id>>1, c=id&1;
                float4 v=*(const float4*)(eb+(size_t)m*DE+s*8+4*c);
                float* p=xs+(4*c)*516+m;
                p[0]=v.x; p[516]=v.y; p[1032]=v.z; p[1548]=v.w;
            }
            __syncthreads();
            #pragma unroll
            for (int il=0;il<8;il++){
                ulonglong2 X=*(const ulonglong2*)(xs+il*516+4*t);
                const ulonglong2* A=(const ulonglong2*)(qk2+(n*DKE+DK+s*8+il)*8);
                ulonglong2 a0=A[0],a1=A[1],a2=A[2],a3=A[3];
                fma2(acc[n][0][0],a0.x,X.x); fma2(acc[n][0][1],a0.x,X.y);
                fma2(acc[n][1][0],a0.y,X.x); fma2(acc[n][1][1],a0.y,X.y);
                fma2(acc[n][2][0],a1.x,X.x); fma2(acc[n][2][1],a1.x,X.y);
                fma2(acc[n][3][0],a1.y,X.x); fma2(acc[n][3][1],a1.y,X.y);
                fma2(acc[n][4][0],a2.x,X.x); fma2(acc[n][4][1],a2.x,X.y);
                fma2(acc[n][5][0],a2.y,X.x); fma2(acc[n][5][1],a2.y,X.y);
                fma2(acc[n][6][0],a3.x,X.x); fma2(acc[n][6][1],a3.x,X.y);
                fma2(acc[n][7][0],a3.y,X.x); fma2(acc[n][7][1],a3.y,X.y);
            }
        }
    }
    __syncthreads();

    // ---- softmax over m (register logits, block reduce) ----
    #pragma unroll
    for (int n=0;n<2;n++)
        #pragma unroll
        for (int h=0;h<8;h++){
            float2 p0=unpack2(acc[n][h][0]), p1=unpack2(acc[n][h][1]);
            float mx=fmaxf(fmaxf(p0.x,p0.y),fmaxf(p1.x,p1.y));
            #pragma unroll
            for (int s=16;s>0;s>>=1) mx=fmaxf(mx,__shfl_xor_sync(0xffffffffu,mx,s));
            if (l==0) redA[(n*8+h)*4+w]=mx;
        }
    __syncthreads();
    #pragma unroll
    for (int n=0;n<2;n++)
        #pragma unroll
        for (int h=0;h<8;h++){
            const int c=n*8+h;
            float gm=fmaxf(fmaxf(redA[c*4+0],redA[c*4+1]),
                           fmaxf(redA[c*4+2],redA[c*4+3]));
            float2 p0=unpack2(acc[n][h][0]), p1=unpack2(acc[n][h][1]);
            p0.x=__expf(p0.x-gm); p0.y=__expf(p0.y-gm);
            p1.x=__expf(p1.x-gm); p1.y=__expf(p1.y-gm);
            acc[n][h][0]=pack2(p0.x,p0.y);
            acc[n][h][1]=pack2(p1.x,p1.y);
            float sum=(p0.x+p0.y)+(p1.x+p1.y);
            #pragma unroll
            for (int s=16;s>0;s>>=1) sum+=__shfl_xor_sync(0xffffffffu,sum,s);
            if (l==0) redB[c*4+w]=sum;
        }
    __syncthreads();
    #pragma unroll
    for (int n=0;n<2;n++)
        #pragma unroll
        for (int h=0;h<8;h++){
            const int c=n*8+h;
            float inv=1.f/(redB[c*4+0]+redB[c*4+1]+redB[c*4+2]+redB[c*4+3]);
            float2 p0=unpack2(acc[n][h][0]), p1=unpack2(acc[n][h][1]);
            float4 o=make_float4(p0.x*inv,p0.y*inv,p1.x*inv,p1.y*inv);
            *(float4*)(g_attn+(((size_t)b*H+h)*N+n0+n)*M+4*t)=o;
        }
}

// ---------------------------------------------------------------------------
// K3: mh = attn @ v   (256 blocks; vv as single LDS.128)
// ---------------------------------------------------------------------------
__global__ __launch_bounds__(256) void k_av() {
    const int x=blockIdx.x, b=x>>7, h=(x>>4)&7, n0=(x&15)<<5;
    const int t=threadIdx.x, nl=t>>3, og=t&7;
    __shared__ __align__(16) float at[32][132];
    __shared__ __align__(16) float vt[128][32];
    u64 a01=0ull, a23=0ull;
    for (int mt=0;mt<4;mt++){
        const int mb=mt<<7;
        #pragma unroll
        for (int j=0;j<4;j++){int idx=t+256*j,r=idx>>5,c=idx&31;
            *(float4*)&at[r][c*4]=
                *(const float4*)(g_attn+(((size_t)b*H+h)*N+n0+r)*M+mb+c*4);}
        #pragma unroll
        for (int j=0;j<4;j++){int idx=t+256*j,ml=idx>>3,c=idx&7;
            *(float4*)&vt[ml][c*4]=
                *(const float4*)(g_v+(((size_t)b*M+mb+ml)*H+h)*O+c*4);}
        __syncthreads();
        #pragma unroll 8
        for (int m=0;m<128;m++){
            float a=at[nl][m];
            u64 a2=pack2(a,a);
            ulonglong2 V=*(const ulonglong2*)&vt[m][og*4];
            fma2(a01,a2,V.x);
            fma2(a23,a2,V.y);
        }
        __syncthreads();
    }
    float2 x01=unpack2(a01), x23=unpack2(a23);
    float4 outv=make_float4(x01.x,x01.y,x23.x,x23.y);
    *(float4*)&g_mh[((size_t)(b*N+n0+nl)*H+h)*O+og*4]=outv;
}

// ---------------------------------------------------------------------------
// K4: out = mh @ Wp + bias
// ---------------------------------------------------------------------------
__global__ __launch_bounds__(256) void k_proj(const float* __restrict__ Wp,
                                              const float* __restrict__ bias,
                                              float* __restrict__ out) {
    const int b=blockIdx.x>>6, n0=(blockIdx.x&63)<<3, t=threadIdx.x;
    __shared__ float mh[8][H*O];
    #pragma unroll
    for (int j=0;j<8;j++){int idx=t+256*j,nl=idx>>8,c=idx&255;
        mh[nl][c]=g_mh[((size_t)(b*N+n0+nl))*(H*O)+c];}
    __syncthreads();
    const int jj=t&127, half=t>>7;
    const float bv=bias[jj];
    #pragma unroll
    for (int pass=0;pass<4;pass++){
        int nl=half+2*pass;
        float acc=0.f;
        for (int k=0;k<H*O;k++)
            acc=fmaf(mh[nl][k],Wp[(size_t)k*OUTD+jj],acc);
        out[((size_t)(b*N+n0+nl))*OUTD+jj]=acc+bv;
    }
}

extern "C" void kernel_launch(void* const* d_in, const int* in_sizes, int n_in,
                              void* d_out, int out_size) {
    (void)in_sizes; (void)n_in; (void)out_size;
    const float* query=(const float*)d_in[0];
    const float* key  =(const float*)d_in[1];
    const float* value=(const float*)d_in[2];
    const float* edge =(const float*)d_in[3];
    const float* Wq   =(const float*)d_in[4];
    const float* Wk   =(const float*)d_in[5];
    const float* Wv   =(const float*)d_in[6];
    const float* Wp   =(const float*)d_in[7];
    const float* bias =(const float*)d_in[8];
    float* out=(float*)d_out;

    k_pre <<<384,        256>>>(key,query,Wq,Wk,value,Wv);
    k_attn<<<B*(N/2),    128>>>(edge);
    k_av  <<<B*H*(N/32), 256>>>();
    k_proj<<<B*(N/8),    256>>>(Wp,bias,out);
}

// round 9
// speedup vs baseline: 1.3481x; 1.0945x over previous
#include <cuda_runtime.h>

namespace {
constexpr int B=2, N=512, M=512, DQ=128, DK=128, DE=64, DKE=192, H=8, O=32, OUTD=128;
}

__device__ __align__(16) float g_qk  [(size_t)B*N*DKE*H];   // [b][n][i][h]
__device__ __align__(16) float g_keyT[(size_t)B*DK*M];      // [b][i][m]
__device__ __align__(16) float g_v   [(size_t)B*M*H*O];     // [b][m][h][o]
__device__ __align__(16) float g_attn[(size_t)B*H*N*M];
__device__ __align__(16) float g_mh  [(size_t)B*N*H*O];

typedef unsigned long long u64;
__device__ __forceinline__ u64 pack2(float lo, float hi) {
    u64 r; asm("mov.b64 %0, {%1,%2};" : "=l"(r) : "f"(lo), "f"(hi)); return r;
}
__device__ __forceinline__ void fma2(u64& d, u64 a, u64 b) {
    asm("fma.rn.f32x2 %0, %1, %2, %0;" : "+l"(d) : "l"(a), "l"(b));
}
__device__ __forceinline__ float2 unpack2(u64 v) {
    float2 r; asm("mov.b64 {%0,%1}, %2;" : "=f"(r.x), "=f"(r.y) : "l"(v)); return r;
}

// ---------------------------------------------------------------------------
// K_pre: fused keyT (blocks 0..127) | qk (128..255) | v (256..383)
// ---------------------------------------------------------------------------
__global__ __launch_bounds__(256) void k_pre(const float* __restrict__ key,
                                             const float* __restrict__ query,
                                             const float* __restrict__ Wq,
                                             const float* __restrict__ Wk,
                                             const float* __restrict__ value,
                                             const float* __restrict__ Wv) {
    __shared__ float sm[3072];
    const int t = threadIdx.x;

    if (blockIdx.x < 128) {            // ---- keyT: 32x32 transpose tiles ----
        float (*ts)[33] = (float(*)[33])sm;
        const int x=blockIdx.x, b=x>>6, mt=(x&63)>>2, it=x&3;
        const int m0=mt<<5, i0=it<<5;
        #pragma unroll
        for (int j=0;j<4;j++){int idx=t+256*j,r=idx>>5,c=idx&31;
            ts[r][c]=key[((size_t)b*M+m0+r)*DK+i0+c];}
        __syncthreads();
        #pragma unroll
        for (int j=0;j<4;j++){int idx=t+256*j,r=idx>>5,c=idx&31;
            g_keyT[((size_t)b*DK+i0+r)*M+m0+c]=ts[c][r];}
    } else if (blockIdx.x < 256) {     // ---- qk ----
        float (*xs)[DQ]  = (float(*)[DQ])sm;
        float (*qs)[H*O] = (float(*)[H*O])(sm + 8*DQ);
        const int xb=blockIdx.x-128, b=xb>>6, n0=(xb&63)<<3;
        #pragma unroll
        for (int j=0;j<4;j++){int idx=t+256*j,nl=idx>>7,d=idx&127;
            xs[nl][d]=query[((size_t)(b*N+n0+nl))*DQ+d];}
        __syncthreads();
        {
            const int h=t>>5,o=t&31;
            float acc[8];
            #pragma unroll
            for (int nl=0;nl<8;nl++) acc[nl]=0.f;
            const float* wq=Wq+((size_t)h*DQ)*O+o;
            for (int d=0;d<DQ;d++){float w=wq[(size_t)d*O];
                #pragma unroll
                for (int nl=0;nl<8;nl++) acc[nl]=fmaf(xs[nl][d],w,acc[nl]);}
            const float scale=0.17677669529663688f; // 1/sqrt(32)
            #pragma unroll
            for (int nl=0;nl<8;nl++) qs[nl][t]=acc[nl]*scale;
        }
        __syncthreads();
        #pragma unroll
        for (int j=0;j<6;j++){
            int p=t+256*j,h=p/DKE,i=p-h*DKE;
            const float* wk=Wk+((size_t)h*DKE+i)*O;
            float acc[8];
            #pragma unroll
            for (int nl=0;nl<8;nl++) acc[nl]=0.f;
            for (int o=0;o<O;o++){float w=wk[o];
                #pragma unroll
                for (int nl=0;nl<8;nl++) acc[nl]=fmaf(qs[nl][h*O+o],w,acc[nl]);}
            #pragma unroll
            for (int nl=0;nl<8;nl++)
                g_qk[((size_t)(b*N+n0+nl)*DKE+i)*H+h]=acc[nl];
        }
    } else {                           // ---- v ----
        float (*xs)[DK] = (float(*)[DK])sm;
        const int xb=blockIdx.x-256, b=xb>>6, m0=(xb&63)<<3;
        #pragma unroll
        for (int j=0;j<4;j++){int idx=t+256*j,ml=idx>>7,d=idx&127;
            xs[ml][d]=value[((size_t)(b*M+m0+ml))*DK+d];}
        __syncthreads();
        const int h=t>>5,o=t&31;
        float acc[8];
        #pragma unroll
        for (int ml=0;ml<8;ml++) acc[ml]=0.f;
        const float* wv=Wv+((size_t)h*DK)*O+o;
        for (int d=0;d<DK;d++){float w=wv[(size_t)d*O];
            #pragma unroll
            for (int ml=0;ml<8;ml++) acc[ml]=fmaf(xs[ml][d],w,acc[ml]);}
        #pragma unroll
        for (int ml=0;ml<8;ml++)
            g_v[(((size_t)(b*M+m0+ml))*H+h)*O+o]=acc[ml];
    }
}

// ---------------------------------------------------------------------------
// K2 v4 (unchanged from R7 winner): block = 2 n, 128 threads, m-quad/thread.
// ---------------------------------------------------------------------------
__global__ __launch_bounds__(128,4) void k_attn(const float* __restrict__ edge) {
    __shared__ __align__(16) u64   qk2[2*DKE*H];   // 24.6 KB [n][i][h] pairs
    __shared__ __align__(16) float xs[8*516];      // 16.5 KB edge slice [i][m]
    __shared__ float redA[16*4], redB[16*4];

    const int x=blockIdx.x;            // B*N/2 = 512
    const int b=x>>8, n0=(x&255)<<1, t=threadIdx.x;
    const int w=t>>5, l=t&31;

    const float* gq=g_qk+(size_t)(b*N+n0)*(DKE*H);
    #pragma unroll
    for (int j=0;j<24;j++){float v=gq[t+128*j]; qk2[t+128*j]=pack2(v,v);}
    __syncthreads();

    u64 acc[2][8][2];
    #pragma unroll
    for (int n=0;n<2;n++)
        #pragma unroll
        for (int h=0;h<8;h++){acc[n][h][0]=0ull;acc[n][h][1]=0ull;}

    // ---- key phase ----
    {
        const ulonglong2* kT=(const ulonglong2*)(g_keyT+(size_t)b*DK*M);
        #pragma unroll 2
        for (int i=0;i<DK;i++){
            ulonglong2 X=kT[i*(M/4)+t];
            #pragma unroll
            for (int n=0;n<2;n++){
                const ulonglong2* A=(const ulonglong2*)(qk2+(n*DKE+i)*8);
                ulonglong2 a0=A[0],a1=A[1],a2=A[2],a3=A[3];
                fma2(acc[n][0][0],a0.x,X.x); fma2(acc[n][0][1],a0.x,X.y);
                fma2(acc[n][1][0],a0.y,X.x); fma2(acc[n][1][1],a0.y,X.y);
                fma2(acc[n][2][0],a1.x,X.x); fma2(acc[n][2][1],a1.x,X.y);
                fma2(acc[n][3][0],a1.y,X.x); fma2(acc[n][3][1],a1.y,X.y);
                fma2(acc[n][4][0],a2.x,X.x); fma2(acc[n][4][1],a2.x,X.y);
                fma2(acc[n][5][0],a2.y,X.x); fma2(acc[n][5][1],a2.y,X.y);
                fma2(acc[n][6][0],a3.x,X.x); fma2(acc[n][6][1],a3.x,X.y);
                fma2(acc[n][7][0],a3.y,X.x); fma2(acc[n][7][1],a3.y,X.y);
            }
        }
    }

    // ---- edge phase: per n, 8 slices of 8 i ----
    for (int n=0;n<2;n++){
        const float* eb=edge+((size_t)(b*N+n0+n)*M)*DE;
        for (int s=0;s<8;s++){
            __syncthreads();
            #pragma unroll
            for (int r=0;r<8;r++){
                int id=r*128+t, m=id>>1, c=id&1;
                float4 v=*(const float4*)(eb+(size_t)m*DE+s*8+4*c);
                float* p=xs+(4*c)*516+m;
                p[0]=v.x; p[516]=v.y; p[1032]=v.z; p[1548]=v.w;
            }
            __syncthreads();
            #pragma unroll
            for (int il=0;il<8;il++){
                ulonglong2 X=*(const ulonglong2*)(xs+il*516+4*t);
                const ulonglong2* A=(const ulonglong2*)(qk2+(n*DKE+DK+s*8+il)*8);
                ulonglong2 a0=A[0],a1=A[1],a2=A[2],a3=A[3];
                fma2(acc[n][0][0],a0.x,X.x); fma2(acc[n][0][1],a0.x,X.y);
                fma2(acc[n][1][0],a0.y,X.x); fma2(acc[n][1][1],a0.y,X.y);
                fma2(acc[n][2][0],a1.x,X.x); fma2(acc[n][2][1],a1.x,X.y);
                fma2(acc[n][3][0],a1.y,X.x); fma2(acc[n][3][1],a1.y,X.y);
                fma2(acc[n][4][0],a2.x,X.x); fma2(acc[n][4][1],a2.x,X.y);
                fma2(acc[n][5][0],a2.y,X.x); fma2(acc[n][5][1],a2.y,X.y);
                fma2(acc[n][6][0],a3.x,X.x); fma2(acc[n][6][1],a3.x,X.y);
                fma2(acc[n][7][0],a3.y,X.x); fma2(acc[n][7][1],a3.y,X.y);
            }
        }
    }
    __syncthreads();

    // ---- softmax over m (register logits, block reduce) ----
    #pragma unroll
    for (int n=0;n<2;n++)
        #pragma unroll
        for (int h=0;h<8;h++){
            float2 p0=unpack2(acc[n][h][0]), p1=unpack2(acc[n][h][1]);
            float mx=fmaxf(fmaxf(p0.x,p0.y),fmaxf(p1.x,p1.y));
            #pragma unroll
            for (int s=16;s>0;s>>=1) mx=fmaxf(mx,__shfl_xor_sync(0xffffffffu,mx,s));
            if (l==0) redA[(n*8+h)*4+w]=mx;
        }
    __syncthreads();
    #pragma unroll
    for (int n=0;n<2;n++)
        #pragma unroll
        for (int h=0;h<8;h++){
            const int c=n*8+h;
            float gm=fmaxf(fmaxf(redA[c*4+0],redA[c*4+1]),
                           fmaxf(redA[c*4+2],redA[c*4+3]));
            float2 p0=unpack2(acc[n][h][0]), p1=unpack2(acc[n][h][1]);
            p0.x=__expf(p0.x-gm); p0.y=__expf(p0.y-gm);
            p1.x=__expf(p1.x-gm); p1.y=__expf(p1.y-gm);
            acc[n][h][0]=pack2(p0.x,p0.y);
            acc[n][h][1]=pack2(p1.x,p1.y);
            float sum=(p0.x+p0.y)+(p1.x+p1.y);
            #pragma unroll
            for (int s=16;s>0;s>>=1) sum+=__shfl_xor_sync(0xffffffffu,sum,s);
            if (l==0) redB[c*4+w]=sum;
        }
    __syncthreads();
    #pragma unroll
    for (int n=0;n<2;n++)
        #pragma unroll
        for (int h=0;h<8;h++){
            const int c=n*8+h;
            float inv=1.f/(redB[c*4+0]+redB[c*4+1]+redB[c*4+2]+redB[c*4+3]);
            float2 p0=unpack2(acc[n][h][0]), p1=unpack2(acc[n][h][1]);
            float4 o=make_float4(p0.x*inv,p0.y*inv,p1.x*inv,p1.y*inv);
            *(float4*)(g_attn+(((size_t)b*H+h)*N+n0+n)*M+4*t)=o;
        }
}

// ---------------------------------------------------------------------------
// K3 v2: mh = attn @ v. 512 blocks (b,h,16-n), 128 threads -> ~50% occ.
// ---------------------------------------------------------------------------
__global__ __launch_bounds__(128) void k_av() {
    const int x=blockIdx.x;              // 2*8*32 = 512
    const int b=x>>8, h=(x>>5)&7, n0=(x&31)<<4;
    const int t=threadIdx.x, nl=t>>3, og=t&7;
    __shared__ __align__(16) float at[16][132];
    __shared__ __align__(16) float vt[128][32];
    u64 a01=0ull, a23=0ull;
    for (int mt=0;mt<4;mt++){
        const int mb=mt<<7;
        #pragma unroll
        for (int j=0;j<4;j++){int idx=t+128*j,r=idx>>5,c=idx&31;
            *(float4*)&at[r][c*4]=
                *(const float4*)(g_attn+(((size_t)b*H+h)*N+n0+r)*M+mb+c*4);}
        #pragma unroll
        for (int j=0;j<8;j++){int idx=t+128*j,ml=idx>>3,c=idx&7;
            *(float4*)&vt[ml][c*4]=
                *(const float4*)(g_v+(((size_t)b*M+mb+ml)*H+h)*O+c*4);}
        __syncthreads();
        #pragma unroll 8
        for (int m=0;m<128;m++){
            float a=at[nl][m];
            u64 a2=pack2(a,a);
            ulonglong2 V=*(const ulonglong2*)&vt[m][og*4];
            fma2(a01,a2,V.x);
            fma2(a23,a2,V.y);
        }
        __syncthreads();
    }
    float2 x01=unpack2(a01), x23=unpack2(a23);
    float4 outv=make_float4(x01.x,x01.y,x23.x,x23.y);
    *(float4*)&g_mh[((size_t)(b*N+n0+nl)*H+h)*O+og*4]=outv;
}

// ---------------------------------------------------------------------------
// K4 v2: out = mh @ Wp + bias. 512 blocks (2 n each), 256 thr = (jj, khalf).
// Coalesced Wp loads, 2 FMA per load, smem reduce of k-halves.
// ---------------------------------------------------------------------------
__global__ __launch_bounds__(256) void k_proj(const float* __restrict__ Wp,
                                              const float* __restrict__ bias,
                                              float* __restrict__ out) {
    const int x=blockIdx.x;              // B*N/2 = 512
    const int b=x>>8, n0=(x&255)<<1, t=threadIdx.x;
    const int jj=t&127, kh=t>>7;
    __shared__ float mhs[2][H*O];
    __shared__ float red[2][128];

    #pragma unroll
    for (int j=0;j<2;j++){
        int idx=t+256*j, nl=idx>>8, c=idx&255;
        mhs[nl][c]=g_mh[(size_t)(b*N+n0+nl)*(H*O)+c];
    }
    __syncthreads();

    float acc0=0.f, acc1=0.f;
    const float* wp=Wp+(size_t)(kh*128)*OUTD+jj;
    const float* m0=&mhs[0][kh*128];
    const float* m1=&mhs[1][kh*128];
    #pragma unroll 8
    for (int k=0;k<128;k++){
        float w=wp[(size_t)k*OUTD];
        acc0=fmaf(m0[k],w,acc0);
        acc1=fmaf(m1[k],w,acc1);
    }
    if (kh==1){ red[0][jj]=acc0; red[1][jj]=acc1; }
    __syncthreads();
    if (kh==0){
        float bv=bias[jj];
        out[(size_t)(b*N+n0+0)*OUTD+jj]=acc0+red[0][jj]+bv;
        out[(size_t)(b*N+n0+1)*OUTD+jj]=acc1+red[1][jj]+bv;
    }
}

extern "C" void kernel_launch(void* const* d_in, const int* in_sizes, int n_in,
                              void* d_out, int out_size) {
    (void)in_sizes; (void)n_in; (void)out_size;
    const float* query=(const float*)d_in[0];
    const float* key  =(const float*)d_in[1];
    const float* value=(const float*)d_in[2];
    const float* edge =(const float*)d_in[3];
    const float* Wq   =(const float*)d_in[4];
    const float* Wk   =(const float*)d_in[5];
    const float* Wv   =(const float*)d_in[6];
    const float* Wp   =(const float*)d_in[7];
    const float* bias =(const float*)d_in[8];
    float* out=(float*)d_out;

    k_pre <<<384,        256>>>(key,query,Wq,Wk,value,Wv);
    k_attn<<<B*(N/2),    128>>>(edge);
    k_av  <<<B*H*(N/16), 128>>>();
    k_proj<<<B*(N/2),    256>>>(Wp,bias,out);
}